// round 14
// baseline (speedup 1.0000x reference)
#include <cuda_runtime.h>
#include <math.h>

// ---------------- problem constants ----------------
#define NMAX 50000
#define EMAX 800000
#define CH   128
#define LOUT 64
#define SCHUNK 1024   // counts per scan block
#define BKC  16       // GEMM k-chunk

// ---------------- device scratch ----------------
struct alignas(8) Edge { int s; float nm; };
__device__ unsigned long long g_pk[NMAX];  // packed (count<<44 | wsum*2^32); zeroed by scan3
__device__ float g_dis[NMAX];
__device__ float g_selfnorm[NMAX];
__device__ int   g_rowstart[NMAX + 1];
__device__ int   g_cursor[NMAX];
__device__ int   g_partial[64];
__device__ Edge  g_csr[EMAX];
__device__ float g_act[(size_t)NMAX * CH];
__device__ float g_agg[(size_t)NMAX * CH];
__device__ float g_bnsum[CH];
__device__ float g_bnsq[CH];
__device__ float g_scale[CH];
__device__ float g_shift[CH];
__device__ int   g_ticket;
// pre-split weights (tf32 hi/lo): W0 @0, W1 @16384, Wf @32768
__device__ unsigned g_Whi[128 * (128 + 128 + 64)];
__device__ unsigned g_Wlo[128 * (128 + 128 + 64)];

// ---------------- helpers ----------------
__device__ __forceinline__ bool idx_is64(const void* ei) {
    const int* w = (const int*)ei;
    return ((w[1] | w[3] | w[5] | w[7] | w[9]) == 0);
}
__device__ __forceinline__ int fetch_idx(const void* p, long long i, bool is64) {
    if (is64) return (int)((const long long*)p)[i];
    return ((const int*)p)[i];
}
__device__ __forceinline__ void cvt2tf32(float x, unsigned& hi, unsigned& lo) {
    asm("cvt.rna.tf32.f32 %0, %1;" : "=r"(hi) : "f"(x));
    float l = x - __uint_as_float(hi);
    asm("cvt.rna.tf32.f32 %0, %1;" : "=r"(lo) : "f"(l));
}
__device__ __forceinline__ void mma_tf32(float* c, const unsigned* a, unsigned b0, unsigned b1) {
    asm volatile("mma.sync.aligned.m16n8k8.row.col.f32.tf32.tf32.f32 "
        "{%0,%1,%2,%3}, {%4,%5,%6,%7}, {%8,%9}, {%0,%1,%2,%3};"
        : "+f"(c[0]), "+f"(c[1]), "+f"(c[2]), "+f"(c[3])
        : "r"(a[0]), "r"(a[1]), "r"(a[2]), "r"(a[3]), "r"(b0), "r"(b1));
}

// ---------------- fused: degree accumulation + weight pre-split ----------------
__global__ void k_deg(const void* ei, const float* __restrict__ ew, int E,
                      const float* __restrict__ W0, const float* __restrict__ W1,
                      const float* __restrict__ Wf) {
    // blocks 0..63 also pre-split weights (grid-stride extra duty)
    if (blockIdx.x < 64) {
        int i = blockIdx.x * 256 + threadIdx.x;
        if (i < 128 * 128) {
            unsigned hi, lo;
            cvt2tf32(W0[i], hi, lo); g_Whi[i] = hi;          g_Wlo[i] = lo;
            cvt2tf32(W1[i], hi, lo); g_Whi[16384 + i] = hi;  g_Wlo[16384 + i] = lo;
            if (i < 128 * 64) {
                cvt2tf32(Wf[i], hi, lo); g_Whi[32768 + i] = hi; g_Wlo[32768 + i] = lo;
            }
        }
    }
    int e = blockIdx.x * blockDim.x + threadIdx.x;
    if (e >= E) return;
    bool is64 = idx_is64(ei);
    int d = fetch_idx(ei, (long long)E + e, is64);
    unsigned long long p = (1ull << 44) |
        (unsigned long long)(ew[e] * 4294967296.0f);   // w*2^32 < 2^32 (w<1)
    atomicAdd(&g_pk[d], p);
}

// ---------------- parallel scan phases ----------------
__global__ __launch_bounds__(256) void k_scan1(int N) {
    int base = blockIdx.x * SCHUNK + threadIdx.x * 4;
    int s = 0;
    #pragma unroll
    for (int k = 0; k < 4; k++) { int i = base + k; if (i < N) s += (int)(g_pk[i] >> 44); }
    #pragma unroll
    for (int o = 16; o > 0; o >>= 1) s += __shfl_down_sync(0xffffffffu, s, o);
    __shared__ int ws[8];
    if ((threadIdx.x & 31) == 0) ws[threadIdx.x >> 5] = s;
    __syncthreads();
    if (threadIdx.x < 8) {
        int v = ws[threadIdx.x];
        #pragma unroll
        for (int o = 4; o > 0; o >>= 1) v += __shfl_down_sync(0xffu, v, o, 8);
        if (threadIdx.x == 0) g_partial[blockIdx.x] = v;
    }
}

__global__ void k_scan2(int nb) {
    __shared__ int sh[64];
    int t = threadIdx.x;
    int v = (t < nb) ? g_partial[t] : 0;
    sh[t] = v;
    __syncthreads();
    #pragma unroll
    for (int o = 1; o < 64; o <<= 1) {
        int u = (t >= o) ? sh[t - o] : 0;
        __syncthreads();
        sh[t] += u;
        __syncthreads();
    }
    g_partial[t] = sh[t] - v;
}

__global__ __launch_bounds__(256) void k_scan3(int N, int E) {
    const unsigned long long M44 = (1ull << 44) - 1ull;
    int t = threadIdx.x, lane = t & 31, w = t >> 5;
    int base = blockIdx.x * SCHUNK + t * 4;
    int c[4]; unsigned long long pk[4]; int s = 0;
    #pragma unroll
    for (int k = 0; k < 4; k++) {
        int i = base + k;
        pk[k] = (i < N) ? g_pk[i] : 0ull;
        c[k] = (int)(pk[k] >> 44);
        s += c[k];
    }
    int incl = s;
    #pragma unroll
    for (int o = 1; o < 32; o <<= 1) {
        int u = __shfl_up_sync(0xffffffffu, incl, o);
        if (lane >= o) incl += u;
    }
    int wexcl = incl - s;
    __shared__ int wtot[8], woff[8];
    if (lane == 31) wtot[w] = incl;
    __syncthreads();
    if (t < 8) {
        int v = wtot[t], iv = v;
        #pragma unroll
        for (int o = 1; o < 8; o <<= 1) {
            int u = __shfl_up_sync(0xffu, iv, o, 8);
            if (t >= o) iv += u;
        }
        woff[t] = iv - v;
    }
    __syncthreads();
    int run = g_partial[blockIdx.x] + woff[w] + wexcl;
    #pragma unroll
    for (int k = 0; k < 4; k++) {
        int i = base + k;
        if (i < N) {
            g_rowstart[i] = run;
            g_cursor[i]   = run;
            run += c[k];
            float deg = (float)(pk[k] & M44) * 0x1p-32f;
            float d = rsqrtf(deg + 1.0f);
            g_dis[i] = d;
            g_selfnorm[i] = d * d;
            g_pk[i] = 0ull;
        }
    }
    if (blockIdx.x == 0 && t == 0) g_rowstart[N] = E;
}

__global__ void k_fill(const void* ei, const float* __restrict__ ew, int E) {
    int e = blockIdx.x * blockDim.x + threadIdx.x;
    if (e >= E) return;
    bool is64 = idx_is64(ei);
    int s = fetch_idx(ei, e, is64);
    int d = fetch_idx(ei, (long long)E + e, is64);
    float nm = g_dis[s] * ew[e] * g_dis[d];
    int pos = atomicAdd(&g_cursor[d], 1);
    Edge ed; ed.s = s; ed.nm = nm;
    g_csr[pos] = ed;
}

// ---------------- pipelined tf32 tensor GEMM: out = f(A)[N,128] @ W[128,COUT] ------
// 3-term split. Staging (cvt/STS + prefetch + cp.async) interleaved BETWEEN the two
// ks halves of each chunk so it overlaps tensor work. 2 CTAs/SM.
template<int COUT, bool BN>
__global__ __launch_bounds__(256, 2) void k_gemm(const float* __restrict__ A, int woff,
                                                 float* __restrict__ out, int N) {
    constexpr int AS = 20, BS = COUT + 8, NT = COUT / 16;
    constexpr int ABUF = 128 * AS;
    constexpr int BBUF = BKC * BS;
    constexpr int BITER = (BKC * COUT / 4) / 256;
    extern __shared__ unsigned smem[];
    unsigned* sA_h = smem;
    unsigned* sA_l = smem + 2 * ABUF;
    unsigned* sB_h = smem + 4 * ABUF;
    unsigned* sB_l = smem + 4 * ABUF + 3 * BBUF;
    float* s_scale = (float*)(smem + 4 * ABUF + 6 * BBUF);
    float* s_shift = s_scale + 128;

    int tid = threadIdx.x;
    int lane = tid & 31, w = tid >> 5;
    int wm = w & 3, wn = w >> 2;
    int brow = blockIdx.x * 128;
    int g = lane >> 2, t4 = lane & 3;

    if (BN) {
        if (tid < 128) { s_scale[tid] = g_scale[tid]; s_shift[tid] = g_shift[tid]; }
        __syncthreads();
    }

    int f1 = tid + 256;
    int row0 = tid >> 2, kc0 = (tid & 3) * 4;
    int row1 = f1 >> 2,  kc1 = (f1 & 3) * 4;
    int gr0 = brow + row0, gr1 = brow + row1;
    float4 rA0, rA1;

    auto prefA = [&](int c) {
        rA0 = (gr0 < N) ? *(const float4*)&A[(size_t)gr0 * 128 + c * BKC + kc0]
                        : make_float4(0.f, 0.f, 0.f, 0.f);
        rA1 = (gr1 < N) ? *(const float4*)&A[(size_t)gr1 * 128 + c * BKC + kc1]
                        : make_float4(0.f, 0.f, 0.f, 0.f);
    };
    auto cvtstoreA = [&](int c, int buf) {
        unsigned* dh = sA_h + buf * ABUF;
        unsigned* dl = sA_l + buf * ABUF;
        #pragma unroll
        for (int q = 0; q < 2; q++) {
            float4 v = q ? rA1 : rA0;
            int row = q ? row1 : row0;
            int kc  = q ? kc1 : kc0;
            if (BN) {
                int cb = c * BKC + kc;
                v.x = fmaxf(fmaf(v.x, s_scale[cb + 0], s_shift[cb + 0]), 0.f);
                v.y = fmaxf(fmaf(v.y, s_scale[cb + 1], s_shift[cb + 1]), 0.f);
                v.z = fmaxf(fmaf(v.z, s_scale[cb + 2], s_shift[cb + 2]), 0.f);
                v.w = fmaxf(fmaf(v.w, s_scale[cb + 3], s_shift[cb + 3]), 0.f);
            }
            unsigned hi, lo;
            int b = row * AS + kc;
            cvt2tf32(v.x, hi, lo); dh[b + 0] = hi; dl[b + 0] = lo;
            cvt2tf32(v.y, hi, lo); dh[b + 1] = hi; dl[b + 1] = lo;
            cvt2tf32(v.z, hi, lo); dh[b + 2] = hi; dl[b + 2] = lo;
            cvt2tf32(v.w, hi, lo); dh[b + 3] = hi; dl[b + 3] = lo;
        }
    };
    auto loadB = [&](int c, int buf) {
        #pragma unroll
        for (int it = 0; it < BITER; it++) {
            int f = tid + it * 256;
            int kr = f / (COUT / 4);
            int nc = (f % (COUT / 4)) * 4;
            int gidx = woff + (c * BKC + kr) * COUT + nc;
            unsigned dh = (unsigned)__cvta_generic_to_shared(sB_h + buf * BBUF + kr * BS + nc);
            unsigned dl = (unsigned)__cvta_generic_to_shared(sB_l + buf * BBUF + kr * BS + nc);
            asm volatile("cp.async.cg.shared.global [%0], [%1], 16;" :: "r"(dh), "l"(&g_Whi[gidx]));
            asm volatile("cp.async.cg.shared.global [%0], [%1], 16;" :: "r"(dl), "l"(&g_Wlo[gidx]));
        }
        asm volatile("cp.async.commit_group;");
    };

    float acc[2][NT][4];
    #pragma unroll
    for (int i = 0; i < 2; i++)
        #pragma unroll
        for (int j = 0; j < NT; j++)
            #pragma unroll
            for (int q = 0; q < 4; q++) acc[i][j][q] = 0.f;

    // one ks half (8 k-steps) of chunk buffers
    auto compute_half = [&](const unsigned* Ah, const unsigned* Al,
                            const unsigned* Bh, const unsigned* Bl, int ks) {
        unsigned ah[2][4], al[2][4];
        #pragma unroll
        for (int i = 0; i < 2; i++) {
            int r = wm * 32 + i * 16;
            ah[i][0] = Ah[(r + g) * AS + ks + t4];
            ah[i][1] = Ah[(r + g + 8) * AS + ks + t4];
            ah[i][2] = Ah[(r + g) * AS + ks + t4 + 4];
            ah[i][3] = Ah[(r + g + 8) * AS + ks + t4 + 4];
            al[i][0] = Al[(r + g) * AS + ks + t4];
            al[i][1] = Al[(r + g + 8) * AS + ks + t4];
            al[i][2] = Al[(r + g) * AS + ks + t4 + 4];
            al[i][3] = Al[(r + g + 8) * AS + ks + t4 + 4];
        }
        #pragma unroll
        for (int j = 0; j < NT; j++) {
            int col = wn * (COUT / 2) + j * 8 + g;
            unsigned bh0 = Bh[(ks + t4) * BS + col];
            unsigned bh1 = Bh[(ks + t4 + 4) * BS + col];
            unsigned bl0 = Bl[(ks + t4) * BS + col];
            unsigned bl1 = Bl[(ks + t4 + 4) * BS + col];
            #pragma unroll
            for (int i = 0; i < 2; i++) {
                mma_tf32(acc[i][j], ah[i], bh0, bh1);   // hi*hi
                mma_tf32(acc[i][j], ah[i], bl0, bl1);   // hi*lo
                mma_tf32(acc[i][j], al[i], bh0, bh1);   // lo*hi
            }
        }
    };

    // prologue
    prefA(0);
    loadB(0, 0);
    loadB(1, 1);
    cvtstoreA(0, 0);
    prefA(1);
    asm volatile("cp.async.wait_group 1;");
    __syncthreads();

    #pragma unroll 1
    for (int c = 0; c < 8; c++) {
        const unsigned* Ah = sA_h + (c & 1) * ABUF;
        const unsigned* Al = sA_l + (c & 1) * ABUF;
        const unsigned* Bh = sB_h + (c % 3) * BBUF;
        const unsigned* Bl = sB_l + (c % 3) * BBUF;
        compute_half(Ah, Al, Bh, Bl, 0);
        // staging interleaved: overlaps with the second ks half's tensor work
        if (c < 7) {
            cvtstoreA(c + 1, (c + 1) & 1);
            if (c < 6) { prefA(c + 2); loadB(c + 2, (c + 2) % 3); }
        }
        compute_half(Ah, Al, Bh, Bl, 8);
        if (c < 7) {
            if (c < 6) asm volatile("cp.async.wait_group 1;");
            else       asm volatile("cp.async.wait_group 0;");
            __syncthreads();
        }
    }

    #pragma unroll
    for (int i = 0; i < 2; i++) {
        int r0 = brow + wm * 32 + i * 16 + g;
        #pragma unroll
        for (int j = 0; j < NT; j++) {
            int col = wn * (COUT / 2) + j * 8 + t4 * 2;
            if (r0 < N)
                *(float2*)&out[(size_t)r0 * COUT + col] = make_float2(acc[i][j][0], acc[i][j][1]);
            if (r0 + 8 < N)
                *(float2*)&out[(size_t)(r0 + 8) * COUT + col] = make_float2(acc[i][j][2], acc[i][j][3]);
        }
    }
}

// ---------------- aggregation: out = S * act  (plain, barrier-free, warp/node) ----
template<int W>
__global__ void k_agg(const float* __restrict__ act, float* __restrict__ out, int N) {
    constexpr int V = W / 32;
    int gw   = (blockIdx.x * blockDim.x + threadIdx.x) >> 5;
    int lane = threadIdx.x & 31;
    if (gw >= N) return;

    float sn = g_selfnorm[gw];
    float acc[V];
    if constexpr (V == 4) {
        float4 tv = *(const float4*)&act[(size_t)gw * W + lane * 4];
        acc[0] = sn * tv.x; acc[1] = sn * tv.y; acc[2] = sn * tv.z; acc[3] = sn * tv.w;
    } else {
        float2 tv = *(const float2*)&act[(size_t)gw * W + lane * 2];
        acc[0] = sn * tv.x; acc[1] = sn * tv.y;
    }
    int r0 = g_rowstart[gw], r1 = g_rowstart[gw + 1];
    #pragma unroll 8
    for (int e = r0; e < r1; e++) {
        Edge ed = g_csr[e];
        float nm = ed.nm;
        if constexpr (V == 4) {
            float4 v = *(const float4*)&act[(size_t)ed.s * W + lane * 4];
            acc[0] = fmaf(nm, v.x, acc[0]); acc[1] = fmaf(nm, v.y, acc[1]);
            acc[2] = fmaf(nm, v.z, acc[2]); acc[3] = fmaf(nm, v.w, acc[3]);
        } else {
            float2 v = *(const float2*)&act[(size_t)ed.s * W + lane * 2];
            acc[0] = fmaf(nm, v.x, acc[0]); acc[1] = fmaf(nm, v.y, acc[1]);
        }
    }
    if constexpr (V == 4) {
        *(float4*)&out[(size_t)gw * W + lane * 4] = make_float4(acc[0], acc[1], acc[2], acc[3]);
    } else {
        *(float2*)&out[(size_t)gw * W + lane * 2] = make_float2(acc[0], acc[1]);
    }
}

// ---------------- BN stats + fused param computation (last-block pattern) ----------
template<int COUT>
__global__ __launch_bounds__(256) void k_bnstats(const float* __restrict__ h,
                                                 const float* __restrict__ gam,
                                                 const float* __restrict__ bet,
                                                 int N, float invN) {
    constexpr int REP = 256 / COUT;
    __shared__ float s_s[256], s_q[256];
    __shared__ bool is_last;
    int t = threadIdx.x;
    int c = t & (COUT - 1);
    int rep = t / COUT;
    int chunk = (N + gridDim.x - 1) / gridDim.x;
    int lo = blockIdx.x * chunk;
    int hi = min(lo + chunk, N);
    float s = 0.f, q = 0.f;
    for (int r = lo + rep; r < hi; r += REP) {
        float v = h[(size_t)r * COUT + c];
        s += v;
        q = fmaf(v, v, q);
    }
    s_s[t] = s; s_q[t] = q;
    __syncthreads();
    if (t < COUT) {
        #pragma unroll
        for (int w = 1; w < REP; w++) { s += s_s[t + w * COUT]; q += s_q[t + w * COUT]; }
        atomicAdd(&g_bnsum[t], s);
        atomicAdd(&g_bnsq[t],  q);
    }
    __threadfence();
    if (t == 0) {
        int v = atomicAdd(&g_ticket, 1);
        is_last = (v == (int)gridDim.x - 1);
    }
    __syncthreads();
    if (is_last) {
        if (t == 0) g_ticket = 0;
        if (t < COUT) {
            float ms = atomicAdd(&g_bnsum[t], 0.f);
            float mq = atomicAdd(&g_bnsq[t], 0.f);
            float m  = ms * invN;
            float va = mq * invN - m * m;
            float inv = rsqrtf(va + 1e-5f);
            float sc = gam[t] * inv;
            g_scale[t] = sc;
            g_shift[t] = bet[t] - m * sc;
            g_bnsum[t] = 0.f;
            g_bnsq[t]  = 0.f;
        }
    }
}

// ---------------- final BN+ReLU writing d_out (LOUT channels) ----------------
__global__ void k_bnfinal(const float* __restrict__ h, float* __restrict__ out, int total) {
    int idx = blockIdx.x * blockDim.x + threadIdx.x;
    if (idx >= total) return;
    int c = idx & (LOUT - 1);
    out[idx] = fmaxf(fmaf(h[idx], g_scale[c], g_shift[c]), 0.f);
}

// ---------------- launch ----------------
extern "C" void kernel_launch(void* const* d_in, const int* in_sizes, int n_in,
                              void* d_out, int out_size) {
    const float* x   = (const float*)d_in[0];
    const void*  ei  = d_in[1];
    const float* ew  = (const float*)d_in[2];
    const float* W0  = (const float*)d_in[3];
    const float* ga0 = (const float*)d_in[5];
    const float* be0 = (const float*)d_in[6];
    const float* W1  = (const float*)d_in[7];
    const float* ga1 = (const float*)d_in[9];
    const float* be1 = (const float*)d_in[10];
    const float* Wf  = (const float*)d_in[11];
    const float* gaf = (const float*)d_in[13];
    const float* bef = (const float*)d_in[14];
    // biases d_in[4]/[8]/[12] are dead: BN mean-subtraction cancels them exactly.

    int N = in_sizes[0] / CH;
    int E = in_sizes[2];
    float invN = 1.0f / (float)N;

    float *act_ptr = nullptr, *agg_ptr = nullptr;
    cudaGetSymbolAddress((void**)&act_ptr, g_act);
    cudaGetSymbolAddress((void**)&agg_ptr, g_agg);

    const int SM128 = 94208, SM64 = 69632;
    cudaFuncSetAttribute(k_gemm<CH, false>, cudaFuncAttributeMaxDynamicSharedMemorySize, SM128);
    cudaFuncSetAttribute(k_gemm<CH, true>,  cudaFuncAttributeMaxDynamicSharedMemorySize, SM128);
    cudaFuncSetAttribute(k_gemm<LOUT, true>, cudaFuncAttributeMaxDynamicSharedMemorySize, SM64);

    int nb_e = (E + 255) / 256;
    int nb_scan = (N + SCHUNK - 1) / SCHUNK;
    int gemm_blocks = (N + 127) / 128;
    int agg_blocks  = (N * 32 + 255) / 256;

    // preprocessing (deg + wsplit fused)
    k_deg<<<nb_e, 256>>>(ei, ew, E, W0, W1, Wf);
    k_scan1<<<nb_scan, 256>>>(N);
    k_scan2<<<1, 64>>>(nb_scan);
    k_gemm<CH, false><<<gemm_blocks, 256, SM128>>>(x, 0, act_ptr, N);   // PROFILED SLOT (4th)
    k_scan3<<<nb_scan, 256>>>(N, E);
    k_fill<<<nb_e, 256>>>(ei, ew, E);

    // layer 0
    k_agg<CH><<<agg_blocks, 256>>>(act_ptr, agg_ptr, N);
    k_bnstats<CH><<<296, 256>>>(agg_ptr, ga0, be0, N, invN);

    // layer 1
    k_gemm<CH, true><<<gemm_blocks, 256, SM128>>>(agg_ptr, 16384, act_ptr, N);
    k_agg<CH><<<agg_blocks, 256>>>(act_ptr, agg_ptr, N);
    k_bnstats<CH><<<296, 256>>>(agg_ptr, ga1, be1, N, invN);

    // layer 2 (64-wide agg)
    k_gemm<LOUT, true><<<gemm_blocks, 256, SM64>>>(agg_ptr, 32768, act_ptr, N);
    k_agg<LOUT><<<agg_blocks, 256>>>(act_ptr, agg_ptr, N);
    k_bnstats<LOUT><<<296, 256>>>(agg_ptr, gaf, bef, N, invN);
    k_bnfinal<<<(N * LOUT + 255) / 256, 256>>>(agg_ptr, (float*)d_out, N * LOUT);
}

// round 15
// speedup vs baseline: 1.0394x; 1.0394x over previous
#include <cuda_runtime.h>
#include <math.h>

// ---------------- problem constants ----------------
#define NMAX 50000
#define EMAX 800000
#define CH   128
#define LOUT 64
#define SCHUNK 1024   // counts per scan block
#define BKC  16       // GEMM k-chunk

// ---------------- device scratch ----------------
struct alignas(8) Edge { int s; float nm; };
__device__ unsigned long long g_pk[NMAX];  // packed (count<<44 | wsum*2^32); zeroed by scan3
__device__ float g_dis[NMAX];
__device__ float g_selfnorm[NMAX];
__device__ int   g_rowstart[NMAX + 1];
__device__ int   g_cursor[NMAX];
__device__ int   g_partial[64];
__device__ Edge  g_csr[EMAX];
__device__ float g_act[(size_t)NMAX * CH];
__device__ float g_agg[(size_t)NMAX * CH];
__device__ float g_bnsum[CH];
__device__ float g_bnsq[CH];
__device__ float g_scale[CH];
__device__ float g_shift[CH];
__device__ int   g_ticket;
// pre-split weights (tf32 hi/lo): W0 @0, W1 @16384, Wf @32768
__device__ unsigned g_Whi[128 * (128 + 128 + 64)];
__device__ unsigned g_Wlo[128 * (128 + 128 + 64)];

// ---------------- helpers ----------------
__device__ __forceinline__ bool idx_is64(const void* ei) {
    const int* w = (const int*)ei;
    return ((w[1] | w[3] | w[5] | w[7] | w[9]) == 0);
}
__device__ __forceinline__ int fetch_idx(const void* p, long long i, bool is64) {
    if (is64) return (int)((const long long*)p)[i];
    return ((const int*)p)[i];
}
__device__ __forceinline__ void cvt2tf32(float x, unsigned& hi, unsigned& lo) {
    asm("cvt.rna.tf32.f32 %0, %1;" : "=r"(hi) : "f"(x));
    float l = x - __uint_as_float(hi);
    asm("cvt.rna.tf32.f32 %0, %1;" : "=r"(lo) : "f"(l));
}
__device__ __forceinline__ void mma_tf32(float* c, const unsigned* a, unsigned b0, unsigned b1) {
    asm volatile("mma.sync.aligned.m16n8k8.row.col.f32.tf32.tf32.f32 "
        "{%0,%1,%2,%3}, {%4,%5,%6,%7}, {%8,%9}, {%0,%1,%2,%3};"
        : "+f"(c[0]), "+f"(c[1]), "+f"(c[2]), "+f"(c[3])
        : "r"(a[0]), "r"(a[1]), "r"(a[2]), "r"(a[3]), "r"(b0), "r"(b1));
}

// ---------------- weight pre-split ----------------
__global__ void k_wsplit(const float* __restrict__ W0, const float* __restrict__ W1,
                         const float* __restrict__ Wf) {
    int i = blockIdx.x * 256 + threadIdx.x;
    if (i < 128 * 128) {
        unsigned hi, lo;
        cvt2tf32(W0[i], hi, lo); g_Whi[i] = hi;          g_Wlo[i] = lo;
        cvt2tf32(W1[i], hi, lo); g_Whi[16384 + i] = hi;  g_Wlo[16384 + i] = lo;
        if (i < 128 * 64) {
            cvt2tf32(Wf[i], hi, lo); g_Whi[32768 + i] = hi; g_Wlo[32768 + i] = lo;
        }
    }
}

// ---------------- degree + count: single packed 64-bit atomic ----------------
__global__ void k_deg(const void* ei, const float* __restrict__ ew, int E) {
    int e = blockIdx.x * blockDim.x + threadIdx.x;
    if (e >= E) return;
    bool is64 = idx_is64(ei);
    int d = fetch_idx(ei, (long long)E + e, is64);
    unsigned long long p = (1ull << 44) |
        (unsigned long long)(ew[e] * 4294967296.0f);   // w*2^32 < 2^32 (w<1)
    atomicAdd(&g_pk[d], p);
}

// ---------------- parallel scan phases ----------------
__global__ __launch_bounds__(256) void k_scan1(int N) {
    int base = blockIdx.x * SCHUNK + threadIdx.x * 4;
    int s = 0;
    #pragma unroll
    for (int k = 0; k < 4; k++) { int i = base + k; if (i < N) s += (int)(g_pk[i] >> 44); }
    #pragma unroll
    for (int o = 16; o > 0; o >>= 1) s += __shfl_down_sync(0xffffffffu, s, o);
    __shared__ int ws[8];
    if ((threadIdx.x & 31) == 0) ws[threadIdx.x >> 5] = s;
    __syncthreads();
    if (threadIdx.x < 8) {
        int v = ws[threadIdx.x];
        #pragma unroll
        for (int o = 4; o > 0; o >>= 1) v += __shfl_down_sync(0xffu, v, o, 8);
        if (threadIdx.x == 0) g_partial[blockIdx.x] = v;
    }
}

__global__ void k_scan2(int nb) {
    __shared__ int sh[64];
    int t = threadIdx.x;
    int v = (t < nb) ? g_partial[t] : 0;
    sh[t] = v;
    __syncthreads();
    #pragma unroll
    for (int o = 1; o < 64; o <<= 1) {
        int u = (t >= o) ? sh[t - o] : 0;
        __syncthreads();
        sh[t] += u;
        __syncthreads();
    }
    g_partial[t] = sh[t] - v;
}

__global__ __launch_bounds__(256) void k_scan3(int N, int E) {
    const unsigned long long M44 = (1ull << 44) - 1ull;
    int t = threadIdx.x, lane = t & 31, w = t >> 5;
    int base = blockIdx.x * SCHUNK + t * 4;
    int c[4]; unsigned long long pk[4]; int s = 0;
    #pragma unroll
    for (int k = 0; k < 4; k++) {
        int i = base + k;
        pk[k] = (i < N) ? g_pk[i] : 0ull;
        c[k] = (int)(pk[k] >> 44);
        s += c[k];
    }
    int incl = s;
    #pragma unroll
    for (int o = 1; o < 32; o <<= 1) {
        int u = __shfl_up_sync(0xffffffffu, incl, o);
        if (lane >= o) incl += u;
    }
    int wexcl = incl - s;
    __shared__ int wtot[8], woff[8];
    if (lane == 31) wtot[w] = incl;
    __syncthreads();
    if (t < 8) {
        int v = wtot[t], iv = v;
        #pragma unroll
        for (int o = 1; o < 8; o <<= 1) {
            int u = __shfl_up_sync(0xffu, iv, o, 8);
            if (t >= o) iv += u;
        }
        woff[t] = iv - v;
    }
    __syncthreads();
    int run = g_partial[blockIdx.x] + woff[w] + wexcl;
    #pragma unroll
    for (int k = 0; k < 4; k++) {
        int i = base + k;
        if (i < N) {
            g_rowstart[i] = run;
            g_cursor[i]   = run;
            run += c[k];
            float deg = (float)(pk[k] & M44) * 0x1p-32f;
            float d = rsqrtf(deg + 1.0f);
            g_dis[i] = d;
            g_selfnorm[i] = d * d;
            g_pk[i] = 0ull;
        }
    }
    if (blockIdx.x == 0 && t == 0) g_rowstart[N] = E;
}

__global__ void k_fill(const void* ei, const float* __restrict__ ew, int E) {
    int e = blockIdx.x * blockDim.x + threadIdx.x;
    if (e >= E) return;
    bool is64 = idx_is64(ei);
    int s = fetch_idx(ei, e, is64);
    int d = fetch_idx(ei, (long long)E + e, is64);
    float nm = g_dis[s] * ew[e] * g_dis[d];
    int pos = atomicAdd(&g_cursor[d], 1);
    Edge ed; ed.s = s; ed.nm = nm;
    g_csr[pos] = ed;
}

// ---------------- pipelined tf32 tensor GEMM: out = f(A)[N,128] @ W[128,COUT] ------
// 3-term split. Staging (cvt/STS + prefetch + cp.async) interleaved BETWEEN the two
// ks halves of each chunk so it overlaps tensor work. 2 CTAs/SM.
template<int COUT, bool BN>
__global__ __launch_bounds__(256, 2) void k_gemm(const float* __restrict__ A, int woff,
                                                 float* __restrict__ out, int N) {
    constexpr int AS = 20, BS = COUT + 8, NT = COUT / 16;
    constexpr int ABUF = 128 * AS;
    constexpr int BBUF = BKC * BS;
    constexpr int BITER = (BKC * COUT / 4) / 256;
    extern __shared__ unsigned smem[];
    unsigned* sA_h = smem;
    unsigned* sA_l = smem + 2 * ABUF;
    unsigned* sB_h = smem + 4 * ABUF;
    unsigned* sB_l = smem + 4 * ABUF + 3 * BBUF;
    float* s_scale = (float*)(smem + 4 * ABUF + 6 * BBUF);
    float* s_shift = s_scale + 128;

    int tid = threadIdx.x;
    int lane = tid & 31, w = tid >> 5;
    int wm = w & 3, wn = w >> 2;
    int brow = blockIdx.x * 128;
    int g = lane >> 2, t4 = lane & 3;

    if (BN) {
        if (tid < 128) { s_scale[tid] = g_scale[tid]; s_shift[tid] = g_shift[tid]; }
        __syncthreads();
    }

    int f1 = tid + 256;
    int row0 = tid >> 2, kc0 = (tid & 3) * 4;
    int row1 = f1 >> 2,  kc1 = (f1 & 3) * 4;
    int gr0 = brow + row0, gr1 = brow + row1;
    float4 rA0, rA1;

    auto prefA = [&](int c) {
        rA0 = (gr0 < N) ? *(const float4*)&A[(size_t)gr0 * 128 + c * BKC + kc0]
                        : make_float4(0.f, 0.f, 0.f, 0.f);
        rA1 = (gr1 < N) ? *(const float4*)&A[(size_t)gr1 * 128 + c * BKC + kc1]
                        : make_float4(0.f, 0.f, 0.f, 0.f);
    };
    auto cvtstoreA = [&](int c, int buf) {
        unsigned* dh = sA_h + buf * ABUF;
        unsigned* dl = sA_l + buf * ABUF;
        #pragma unroll
        for (int q = 0; q < 2; q++) {
            float4 v = q ? rA1 : rA0;
            int row = q ? row1 : row0;
            int kc  = q ? kc1 : kc0;
            if (BN) {
                int cb = c * BKC + kc;
                v.x = fmaxf(fmaf(v.x, s_scale[cb + 0], s_shift[cb + 0]), 0.f);
                v.y = fmaxf(fmaf(v.y, s_scale[cb + 1], s_shift[cb + 1]), 0.f);
                v.z = fmaxf(fmaf(v.z, s_scale[cb + 2], s_shift[cb + 2]), 0.f);
                v.w = fmaxf(fmaf(v.w, s_scale[cb + 3], s_shift[cb + 3]), 0.f);
            }
            unsigned hi, lo;
            int b = row * AS + kc;
            cvt2tf32(v.x, hi, lo); dh[b + 0] = hi; dl[b + 0] = lo;
            cvt2tf32(v.y, hi, lo); dh[b + 1] = hi; dl[b + 1] = lo;
            cvt2tf32(v.z, hi, lo); dh[b + 2] = hi; dl[b + 2] = lo;
            cvt2tf32(v.w, hi, lo); dh[b + 3] = hi; dl[b + 3] = lo;
        }
    };
    auto loadB = [&](int c, int buf) {
        #pragma unroll
        for (int it = 0; it < BITER; it++) {
            int f = tid + it * 256;
            int kr = f / (COUT / 4);
            int nc = (f % (COUT / 4)) * 4;
            int gidx = woff + (c * BKC + kr) * COUT + nc;
            unsigned dh = (unsigned)__cvta_generic_to_shared(sB_h + buf * BBUF + kr * BS + nc);
            unsigned dl = (unsigned)__cvta_generic_to_shared(sB_l + buf * BBUF + kr * BS + nc);
            asm volatile("cp.async.cg.shared.global [%0], [%1], 16;" :: "r"(dh), "l"(&g_Whi[gidx]));
            asm volatile("cp.async.cg.shared.global [%0], [%1], 16;" :: "r"(dl), "l"(&g_Wlo[gidx]));
        }
        asm volatile("cp.async.commit_group;");
    };

    float acc[2][NT][4];
    #pragma unroll
    for (int i = 0; i < 2; i++)
        #pragma unroll
        for (int j = 0; j < NT; j++)
            #pragma unroll
            for (int q = 0; q < 4; q++) acc[i][j][q] = 0.f;

    auto compute_half = [&](const unsigned* Ah, const unsigned* Al,
                            const unsigned* Bh, const unsigned* Bl, int ks) {
        unsigned ah[2][4], al[2][4];
        #pragma unroll
        for (int i = 0; i < 2; i++) {
            int r = wm * 32 + i * 16;
            ah[i][0] = Ah[(r + g) * AS + ks + t4];
            ah[i][1] = Ah[(r + g + 8) * AS + ks + t4];
            ah[i][2] = Ah[(r + g) * AS + ks + t4 + 4];
            ah[i][3] = Ah[(r + g + 8) * AS + ks + t4 + 4];
            al[i][0] = Al[(r + g) * AS + ks + t4];
            al[i][1] = Al[(r + g + 8) * AS + ks + t4];
            al[i][2] = Al[(r + g) * AS + ks + t4 + 4];
            al[i][3] = Al[(r + g + 8) * AS + ks + t4 + 4];
        }
        #pragma unroll
        for (int j = 0; j < NT; j++) {
            int col = wn * (COUT / 2) + j * 8 + g;
            unsigned bh0 = Bh[(ks + t4) * BS + col];
            unsigned bh1 = Bh[(ks + t4 + 4) * BS + col];
            unsigned bl0 = Bl[(ks + t4) * BS + col];
            unsigned bl1 = Bl[(ks + t4 + 4) * BS + col];
            #pragma unroll
            for (int i = 0; i < 2; i++) {
                mma_tf32(acc[i][j], ah[i], bh0, bh1);   // hi*hi
                mma_tf32(acc[i][j], ah[i], bl0, bl1);   // hi*lo
                mma_tf32(acc[i][j], al[i], bh0, bh1);   // lo*hi
            }
        }
    };

    // prologue
    prefA(0);
    loadB(0, 0);
    loadB(1, 1);
    cvtstoreA(0, 0);
    prefA(1);
    asm volatile("cp.async.wait_group 1;");
    __syncthreads();

    #pragma unroll 1
    for (int c = 0; c < 8; c++) {
        const unsigned* Ah = sA_h + (c & 1) * ABUF;
        const unsigned* Al = sA_l + (c & 1) * ABUF;
        const unsigned* Bh = sB_h + (c % 3) * BBUF;
        const unsigned* Bl = sB_l + (c % 3) * BBUF;
        compute_half(Ah, Al, Bh, Bl, 0);
        // staging interleaved: overlaps with the second ks half's tensor work
        if (c < 7) {
            cvtstoreA(c + 1, (c + 1) & 1);
            if (c < 6) { prefA(c + 2); loadB(c + 2, (c + 2) % 3); }
        }
        compute_half(Ah, Al, Bh, Bl, 8);
        if (c < 7) {
            if (c < 6) asm volatile("cp.async.wait_group 1;");
            else       asm volatile("cp.async.wait_group 0;");
            __syncthreads();
        }
    }

    #pragma unroll
    for (int i = 0; i < 2; i++) {
        int r0 = brow + wm * 32 + i * 16 + g;
        #pragma unroll
        for (int j = 0; j < NT; j++) {
            int col = wn * (COUT / 2) + j * 8 + t4 * 2;
            if (r0 < N)
                *(float2*)&out[(size_t)r0 * COUT + col] = make_float2(acc[i][j][0], acc[i][j][1]);
            if (r0 + 8 < N)
                *(float2*)&out[(size_t)(r0 + 8) * COUT + col] = make_float2(acc[i][j][2], acc[i][j][3]);
        }
    }
}

// ---------------- aggregation: out = S * act  (plain, barrier-free, warp/node) ----
template<int W>
__global__ void k_agg(const float* __restrict__ act, float* __restrict__ out, int N) {
    constexpr int V = W / 32;
    int gw   = (blockIdx.x * blockDim.x + threadIdx.x) >> 5;
    int lane = threadIdx.x & 31;
    if (gw >= N) return;

    float sn = g_selfnorm[gw];
    float acc[V];
    if constexpr (V == 4) {
        float4 tv = *(const float4*)&act[(size_t)gw * W + lane * 4];
        acc[0] = sn * tv.x; acc[1] = sn * tv.y; acc[2] = sn * tv.z; acc[3] = sn * tv.w;
    } else {
        float2 tv = *(const float2*)&act[(size_t)gw * W + lane * 2];
        acc[0] = sn * tv.x; acc[1] = sn * tv.y;
    }
    int r0 = g_rowstart[gw], r1 = g_rowstart[gw + 1];
    #pragma unroll 4
    for (int e = r0; e < r1; e++) {
        Edge ed = g_csr[e];
        float nm = ed.nm;
        if constexpr (V == 4) {
            float4 v = *(const float4*)&act[(size_t)ed.s * W + lane * 4];
            acc[0] = fmaf(nm, v.x, acc[0]); acc[1] = fmaf(nm, v.y, acc[1]);
            acc[2] = fmaf(nm, v.z, acc[2]); acc[3] = fmaf(nm, v.w, acc[3]);
        } else {
            float2 v = *(const float2*)&act[(size_t)ed.s * W + lane * 2];
            acc[0] = fmaf(nm, v.x, acc[0]); acc[1] = fmaf(nm, v.y, acc[1]);
        }
    }
    if constexpr (V == 4) {
        *(float4*)&out[(size_t)gw * W + lane * 4] = make_float4(acc[0], acc[1], acc[2], acc[3]);
    } else {
        *(float2*)&out[(size_t)gw * W + lane * 2] = make_float2(acc[0], acc[1]);
    }
}

// ---------------- BN stats + fused param computation (last-block pattern) ----------
template<int COUT>
__global__ __launch_bounds__(256) void k_bnstats(const float* __restrict__ h,
                                                 const float* __restrict__ gam,
                                                 const float* __restrict__ bet,
                                                 int N, float invN) {
    constexpr int REP = 256 / COUT;
    __shared__ float s_s[256], s_q[256];
    __shared__ bool is_last;
    int t = threadIdx.x;
    int c = t & (COUT - 1);
    int rep = t / COUT;
    int chunk = (N + gridDim.x - 1) / gridDim.x;
    int lo = blockIdx.x * chunk;
    int hi = min(lo + chunk, N);
    float s = 0.f, q = 0.f;
    for (int r = lo + rep; r < hi; r += REP) {
        float v = h[(size_t)r * COUT + c];
        s += v;
        q = fmaf(v, v, q);
    }
    s_s[t] = s; s_q[t] = q;
    __syncthreads();
    if (t < COUT) {
        #pragma unroll
        for (int w = 1; w < REP; w++) { s += s_s[t + w * COUT]; q += s_q[t + w * COUT]; }
        atomicAdd(&g_bnsum[t], s);
        atomicAdd(&g_bnsq[t],  q);
    }
    __threadfence();
    if (t == 0) {
        int v = atomicAdd(&g_ticket, 1);
        is_last = (v == (int)gridDim.x - 1);
    }
    __syncthreads();
    if (is_last) {
        if (t == 0) g_ticket = 0;
        if (t < COUT) {
            float ms = atomicAdd(&g_bnsum[t], 0.f);
            float mq = atomicAdd(&g_bnsq[t], 0.f);
            float m  = ms * invN;
            float va = mq * invN - m * m;
            float inv = rsqrtf(va + 1e-5f);
            float sc = gam[t] * inv;
            g_scale[t] = sc;
            g_shift[t] = bet[t] - m * sc;
            g_bnsum[t] = 0.f;
            g_bnsq[t]  = 0.f;
        }
    }
}

// ---------------- final BN+ReLU writing d_out (LOUT channels) ----------------
__global__ void k_bnfinal(const float* __restrict__ h, float* __restrict__ out, int total) {
    int idx = blockIdx.x * blockDim.x + threadIdx.x;
    if (idx >= total) return;
    int c = idx & (LOUT - 1);
    out[idx] = fmaxf(fmaf(h[idx], g_scale[c], g_shift[c]), 0.f);
}

// ---------------- launch ----------------
extern "C" void kernel_launch(void* const* d_in, const int* in_sizes, int n_in,
                              void* d_out, int out_size) {
    const float* x   = (const float*)d_in[0];
    const void*  ei  = d_in[1];
    const float* ew  = (const float*)d_in[2];
    const float* W0  = (const float*)d_in[3];
    const float* ga0 = (const float*)d_in[5];
    const float* be0 = (const float*)d_in[6];
    const float* W1  = (const float*)d_in[7];
    const float* ga1 = (const float*)d_in[9];
    const float* be1 = (const float*)d_in[10];
    const float* Wf  = (const float*)d_in[11];
    const float* gaf = (const float*)d_in[13];
    const float* bef = (const float*)d_in[14];
    // biases d_in[4]/[8]/[12] are dead: BN mean-subtraction cancels them exactly.

    int N = in_sizes[0] / CH;
    int E = in_sizes[2];
    float invN = 1.0f / (float)N;

    float *act_ptr = nullptr, *agg_ptr = nullptr;
    cudaGetSymbolAddress((void**)&act_ptr, g_act);
    cudaGetSymbolAddress((void**)&agg_ptr, g_agg);

    const int SM128 = 94208, SM64 = 69632;
    cudaFuncSetAttribute(k_gemm<CH, false>, cudaFuncAttributeMaxDynamicSharedMemorySize, SM128);
    cudaFuncSetAttribute(k_gemm<CH, true>,  cudaFuncAttributeMaxDynamicSharedMemorySize, SM128);
    cudaFuncSetAttribute(k_gemm<LOUT, true>, cudaFuncAttributeMaxDynamicSharedMemorySize, SM64);

    int nb_e = (E + 255) / 256;
    int nb_scan = (N + SCHUNK - 1) / SCHUNK;
    int gemm_blocks = (N + 127) / 128;
    int agg_blocks  = (N * 32 + 255) / 256;

    // preprocessing
    k_wsplit<<<64, 256>>>(W0, W1, Wf);
    k_deg<<<nb_e, 256>>>(ei, ew, E);
    k_scan1<<<nb_scan, 256>>>(N);
    k_gemm<CH, false><<<gemm_blocks, 256, SM128>>>(x, 0, act_ptr, N);   // PROFILED SLOT (4th)
    k_scan2<<<1, 64>>>(nb_scan);
    k_scan3<<<nb_scan, 256>>>(N, E);
    k_fill<<<nb_e, 256>>>(ei, ew, E);

    // layer 0
    k_agg<CH><<<agg_blocks, 256>>>(act_ptr, agg_ptr, N);
    k_bnstats<CH><<<296, 256>>>(agg_ptr, ga0, be0, N, invN);

    // layer 1
    k_gemm<CH, true><<<gemm_blocks, 256, SM128>>>(agg_ptr, 16384, act_ptr, N);
    k_agg<CH><<<agg_blocks, 256>>>(act_ptr, agg_ptr, N);
    k_bnstats<CH><<<296, 256>>>(agg_ptr, ga1, be1, N, invN);

    // layer 2 (64-wide agg)
    k_gemm<LOUT, true><<<gemm_blocks, 256, SM64>>>(agg_ptr, 32768, act_ptr, N);
    k_agg<LOUT><<<agg_blocks, 256>>>(act_ptr, agg_ptr, N);
    k_bnstats<LOUT><<<296, 256>>>(agg_ptr, gaf, bef, N, invN);
    k_bnfinal<<<(N * LOUT + 255) / 256, 256>>>(agg_ptr, (float*)d_out, N * LOUT);
}

// round 16
// speedup vs baseline: 1.0475x; 1.0078x over previous
#include <cuda_runtime.h>
#include <math.h>

// ---------------- problem constants ----------------
#define NMAX 50000
#define EMAX 800000
#define CH   128
#define LOUT 64
#define SCHUNK 1024   // counts per scan block
#define BKC  16       // GEMM k-chunk

// ---------------- device scratch ----------------
struct alignas(8) Edge { int s; float nm; };
__device__ unsigned long long g_pk[NMAX];  // packed (count<<44 | wsum*2^32); zeroed by scan3
__device__ float g_dis[NMAX];
__device__ float g_selfnorm[NMAX];
__device__ int   g_rowstart[NMAX + 1];
__device__ int   g_cursor[NMAX];
__device__ int   g_partial[64];
__device__ Edge  g_csr[EMAX];
__device__ float g_act[(size_t)NMAX * CH];
__device__ float g_agg[(size_t)NMAX * CH];
__device__ float g_bnsum[CH];
__device__ float g_bnsq[CH];
__device__ float g_scale[CH];
__device__ float g_shift[CH];
__device__ int   g_ticket;
// pre-split weights (tf32 hi/lo), N-MAJOR [n][k=128]: W0 @0, W1 @16384, Wf @32768
__device__ unsigned g_Whi[128 * (128 + 128 + 64)];
__device__ unsigned g_Wlo[128 * (128 + 128 + 64)];

// ---------------- helpers ----------------
__device__ __forceinline__ bool idx_is64(const void* ei) {
    const int* w = (const int*)ei;
    return ((w[1] | w[3] | w[5] | w[7] | w[9]) == 0);
}
__device__ __forceinline__ int fetch_idx(const void* p, long long i, bool is64) {
    if (is64) return (int)((const long long*)p)[i];
    return ((const int*)p)[i];
}
__device__ __forceinline__ void cvt2tf32(float x, unsigned& hi, unsigned& lo) {
    asm("cvt.rna.tf32.f32 %0, %1;" : "=r"(hi) : "f"(x));
    float l = x - __uint_as_float(hi);
    asm("cvt.rna.tf32.f32 %0, %1;" : "=r"(lo) : "f"(l));
}
__device__ __forceinline__ void mma_tf32(float* c, const unsigned* a, unsigned b0, unsigned b1) {
    asm volatile("mma.sync.aligned.m16n8k8.row.col.f32.tf32.tf32.f32 "
        "{%0,%1,%2,%3}, {%4,%5,%6,%7}, {%8,%9}, {%0,%1,%2,%3};"
        : "+f"(c[0]), "+f"(c[1]), "+f"(c[2]), "+f"(c[3])
        : "r"(a[0]), "r"(a[1]), "r"(a[2]), "r"(a[3]), "r"(b0), "r"(b1));
}
__device__ __forceinline__ void ldsm_x4(unsigned* r, unsigned addr) {
    asm volatile("ldmatrix.sync.aligned.m8n8.x4.shared.b16 {%0,%1,%2,%3}, [%4];"
        : "=r"(r[0]), "=r"(r[1]), "=r"(r[2]), "=r"(r[3]) : "r"(addr));
}
__device__ __forceinline__ void ldsm_x2(unsigned& r0, unsigned& r1, unsigned addr) {
    asm volatile("ldmatrix.sync.aligned.m8n8.x2.shared.b16 {%0,%1}, [%2];"
        : "=r"(r0), "=r"(r1) : "r"(addr));
}

// ---------------- weight pre-split (N-MAJOR: g_Whi[woff + n*128 + k]) ----------------
__global__ void k_wsplit(const float* __restrict__ W0, const float* __restrict__ W1,
                         const float* __restrict__ Wf) {
    int i = blockIdx.x * 256 + threadIdx.x;      // i = n*128 + k
    if (i < 128 * 128) {
        int n = i >> 7, k = i & 127;
        unsigned hi, lo;
        cvt2tf32(W0[k * 128 + n], hi, lo); g_Whi[i] = hi;         g_Wlo[i] = lo;
        cvt2tf32(W1[k * 128 + n], hi, lo); g_Whi[16384 + i] = hi; g_Wlo[16384 + i] = lo;
        if (n < 64) {
            cvt2tf32(Wf[k * 64 + n], hi, lo);
            g_Whi[32768 + i] = hi; g_Wlo[32768 + i] = lo;
        }
    }
}

// ---------------- degree + count: single packed 64-bit atomic ----------------
__global__ void k_deg(const void* ei, const float* __restrict__ ew, int E) {
    int e = blockIdx.x * blockDim.x + threadIdx.x;
    if (e >= E) return;
    bool is64 = idx_is64(ei);
    int d = fetch_idx(ei, (long long)E + e, is64);
    unsigned long long p = (1ull << 44) |
        (unsigned long long)(ew[e] * 4294967296.0f);   // w*2^32 < 2^32 (w<1)
    atomicAdd(&g_pk[d], p);
}

// ---------------- parallel scan phases ----------------
__global__ __launch_bounds__(256) void k_scan1(int N) {
    int base = blockIdx.x * SCHUNK + threadIdx.x * 4;
    int s = 0;
    #pragma unroll
    for (int k = 0; k < 4; k++) { int i = base + k; if (i < N) s += (int)(g_pk[i] >> 44); }
    #pragma unroll
    for (int o = 16; o > 0; o >>= 1) s += __shfl_down_sync(0xffffffffu, s, o);
    __shared__ int ws[8];
    if ((threadIdx.x & 31) == 0) ws[threadIdx.x >> 5] = s;
    __syncthreads();
    if (threadIdx.x < 8) {
        int v = ws[threadIdx.x];
        #pragma unroll
        for (int o = 4; o > 0; o >>= 1) v += __shfl_down_sync(0xffu, v, o, 8);
        if (threadIdx.x == 0) g_partial[blockIdx.x] = v;
    }
}

__global__ void k_scan2(int nb) {
    __shared__ int sh[64];
    int t = threadIdx.x;
    int v = (t < nb) ? g_partial[t] : 0;
    sh[t] = v;
    __syncthreads();
    #pragma unroll
    for (int o = 1; o < 64; o <<= 1) {
        int u = (t >= o) ? sh[t - o] : 0;
        __syncthreads();
        sh[t] += u;
        __syncthreads();
    }
    g_partial[t] = sh[t] - v;
}

__global__ __launch_bounds__(256) void k_scan3(int N, int E) {
    const unsigned long long M44 = (1ull << 44) - 1ull;
    int t = threadIdx.x, lane = t & 31, w = t >> 5;
    int base = blockIdx.x * SCHUNK + t * 4;
    int c[4]; unsigned long long pk[4]; int s = 0;
    #pragma unroll
    for (int k = 0; k < 4; k++) {
        int i = base + k;
        pk[k] = (i < N) ? g_pk[i] : 0ull;
        c[k] = (int)(pk[k] >> 44);
        s += c[k];
    }
    int incl = s;
    #pragma unroll
    for (int o = 1; o < 32; o <<= 1) {
        int u = __shfl_up_sync(0xffffffffu, incl, o);
        if (lane >= o) incl += u;
    }
    int wexcl = incl - s;
    __shared__ int wtot[8], woff2[8];
    if (lane == 31) wtot[w] = incl;
    __syncthreads();
    if (t < 8) {
        int v = wtot[t], iv = v;
        #pragma unroll
        for (int o = 1; o < 8; o <<= 1) {
            int u = __shfl_up_sync(0xffu, iv, o, 8);
            if (t >= o) iv += u;
        }
        woff2[t] = iv - v;
    }
    __syncthreads();
    int run = g_partial[blockIdx.x] + woff2[w] + wexcl;
    #pragma unroll
    for (int k = 0; k < 4; k++) {
        int i = base + k;
        if (i < N) {
            g_rowstart[i] = run;
            g_cursor[i]   = run;
            run += c[k];
            float deg = (float)(pk[k] & M44) * 0x1p-32f;
            float d = rsqrtf(deg + 1.0f);
            g_dis[i] = d;
            g_selfnorm[i] = d * d;
            g_pk[i] = 0ull;
        }
    }
    if (blockIdx.x == 0 && t == 0) g_rowstart[N] = E;
}

__global__ void k_fill(const void* ei, const float* __restrict__ ew, int E) {
    int e = blockIdx.x * blockDim.x + threadIdx.x;
    if (e >= E) return;
    bool is64 = idx_is64(ei);
    int s = fetch_idx(ei, e, is64);
    int d = fetch_idx(ei, (long long)E + e, is64);
    float nm = g_dis[s] * ew[e] * g_dis[d];
    int pos = atomicAdd(&g_cursor[d], 1);
    Edge ed; ed.s = s; ed.nm = nm;
    g_csr[pos] = ed;
}

// ---------------- pipelined tf32 tensor GEMM: out = f(A)[N,128] @ W[128,COUT] ------
// 3-term split. Fragments loaded via ldmatrix (A k-major 16x8 tiles via x4;
// B n-major 8x8 tiles via x2). Staging interleaved mid-chunk. 2 CTAs/SM.
template<int COUT, bool BN>
__global__ __launch_bounds__(256, 2) void k_gemm(const float* __restrict__ A, int woff,
                                                 float* __restrict__ out, int N) {
    constexpr int AS = 20;               // A row stride (words), rows 80B (16B aligned)
    constexpr int BS = 20;               // B n-row stride (words): 16 k + 4 pad
    constexpr int NT = COUT / 16;
    constexpr int ABUF = 128 * AS;
    constexpr int BBUF = COUT * BS;
    constexpr int BITER = (COUT * 4) / 256;   // 16B segs per chunk / threads (2 or 1)
    extern __shared__ unsigned smem[];
    unsigned* sA_h = smem;
    unsigned* sA_l = smem + 2 * ABUF;
    unsigned* sB_h = smem + 4 * ABUF;
    unsigned* sB_l = smem + 4 * ABUF + 3 * BBUF;
    float* s_scale = (float*)(smem + 4 * ABUF + 6 * BBUF);
    float* s_shift = s_scale + 128;
    unsigned smem32 = (unsigned)__cvta_generic_to_shared(smem);

    int tid = threadIdx.x;
    int lane = tid & 31, w = tid >> 5;
    int wm = w & 3, wn = w >> 2;
    int brow = blockIdx.x * 128;
    int g = lane >> 2, t4 = lane & 3;

    if (BN) {
        if (tid < 128) { s_scale[tid] = g_scale[tid]; s_shift[tid] = g_shift[tid]; }
        __syncthreads();
    }

    // ldmatrix per-thread byte offsets within a tile
    unsigned aoff = ((lane & 15) * AS) * 4 + (lane >> 4) * 16;
    unsigned boff = ((lane & 7) * BS) * 4 + ((lane >> 3) & 1) * 16;

    int f1 = tid + 256;
    int row0 = tid >> 2, kc0 = (tid & 3) * 4;
    int row1 = f1 >> 2,  kc1 = (f1 & 3) * 4;
    int gr0 = brow + row0, gr1 = brow + row1;
    float4 rA0, rA1;

    auto prefA = [&](int c) {
        rA0 = (gr0 < N) ? *(const float4*)&A[(size_t)gr0 * 128 + c * BKC + kc0]
                        : make_float4(0.f, 0.f, 0.f, 0.f);
        rA1 = (gr1 < N) ? *(const float4*)&A[(size_t)gr1 * 128 + c * BKC + kc1]
                        : make_float4(0.f, 0.f, 0.f, 0.f);
    };
    auto cvtstoreA = [&](int c, int buf) {
        unsigned* dh = sA_h + buf * ABUF;
        unsigned* dl = sA_l + buf * ABUF;
        #pragma unroll
        for (int q = 0; q < 2; q++) {
            float4 v = q ? rA1 : rA0;
            int row = q ? row1 : row0;
            int kc  = q ? kc1 : kc0;
            if (BN) {
                int cb = c * BKC + kc;
                v.x = fmaxf(fmaf(v.x, s_scale[cb + 0], s_shift[cb + 0]), 0.f);
                v.y = fmaxf(fmaf(v.y, s_scale[cb + 1], s_shift[cb + 1]), 0.f);
                v.z = fmaxf(fmaf(v.z, s_scale[cb + 2], s_shift[cb + 2]), 0.f);
                v.w = fmaxf(fmaf(v.w, s_scale[cb + 3], s_shift[cb + 3]), 0.f);
            }
            unsigned hi, lo;
            int b = row * AS + kc;
            cvt2tf32(v.x, hi, lo); dh[b + 0] = hi; dl[b + 0] = lo;
            cvt2tf32(v.y, hi, lo); dh[b + 1] = hi; dl[b + 1] = lo;
            cvt2tf32(v.z, hi, lo); dh[b + 2] = hi; dl[b + 2] = lo;
            cvt2tf32(v.w, hi, lo); dh[b + 3] = hi; dl[b + 3] = lo;
        }
    };
    // B chunk c: n-major rows [0..COUT), k cols [c*16..c*16+16); 4 16B segs per row
    auto loadB = [&](int c, int buf) {
        #pragma unroll
        for (int it = 0; it < BITER; it++) {
            int f = tid + it * 256;
            int n = f >> 2;
            int seg = f & 3;
            int gidx = woff + n * 128 + c * BKC + seg * 4;
            unsigned dh = smem32 + (4 * ABUF + buf * BBUF + n * BS + seg * 4) * 4;
            unsigned dl = smem32 + (4 * ABUF + 3 * BBUF + buf * BBUF + n * BS + seg * 4) * 4;
            asm volatile("cp.async.cg.shared.global [%0], [%1], 16;" :: "r"(dh), "l"(&g_Whi[gidx]));
            asm volatile("cp.async.cg.shared.global [%0], [%1], 16;" :: "r"(dl), "l"(&g_Wlo[gidx]));
        }
        asm volatile("cp.async.commit_group;");
    };

    float acc[2][NT][4];
    #pragma unroll
    for (int i = 0; i < 2; i++)
        #pragma unroll
        for (int j = 0; j < NT; j++)
            #pragma unroll
            for (int q = 0; q < 4; q++) acc[i][j][q] = 0.f;

    auto compute_half = [&](int abuf, int bbuf, int ks) {
        unsigned ah[2][4], al[2][4];
        #pragma unroll
        for (int i = 0; i < 2; i++) {
            unsigned off = ((unsigned)((wm * 32 + i * 16) * AS + ks)) * 4 + aoff;
            ldsm_x4(ah[i], smem32 + (abuf * ABUF) * 4 + off);
            ldsm_x4(al[i], smem32 + ((2 + abuf) * ABUF) * 4 + off);
        }
        #pragma unroll
        for (int j = 0; j < NT; j++) {
            unsigned off = ((unsigned)((wn * (COUT / 2) + j * 8) * BS + ks)) * 4 + boff;
            unsigned bh0, bh1, bl0, bl1;
            ldsm_x2(bh0, bh1, smem32 + (4 * ABUF + bbuf * BBUF) * 4 + off);
            ldsm_x2(bl0, bl1, smem32 + (4 * ABUF + (3 + bbuf) * BBUF) * 4 + off);
            #pragma unroll
            for (int i = 0; i < 2; i++) {
                mma_tf32(acc[i][j], ah[i], bh0, bh1);   // hi*hi
                mma_tf32(acc[i][j], ah[i], bl0, bl1);   // hi*lo
                mma_tf32(acc[i][j], al[i], bh0, bh1);   // lo*hi
            }
        }
    };

    // prologue
    prefA(0);
    loadB(0, 0);
    loadB(1, 1);
    cvtstoreA(0, 0);
    prefA(1);
    asm volatile("cp.async.wait_group 1;");
    __syncthreads();

    #pragma unroll 1
    for (int c = 0; c < 8; c++) {
        int abuf = c & 1, bbuf = c % 3;
        compute_half(abuf, bbuf, 0);
        // staging interleaved: overlaps with the second ks half's tensor work
        if (c < 7) {
            cvtstoreA(c + 1, (c + 1) & 1);
            if (c < 6) { prefA(c + 2); loadB(c + 2, (c + 2) % 3); }
        }
        compute_half(abuf, bbuf, 8);
        if (c < 7) {
            if (c < 6) asm volatile("cp.async.wait_group 1;");
            else       asm volatile("cp.async.wait_group 0;");
            __syncthreads();
        }
    }

    #pragma unroll
    for (int i = 0; i < 2; i++) {
        int r0 = brow + wm * 32 + i * 16 + g;
        #pragma unroll
        for (int j = 0; j < NT; j++) {
            int col = wn * (COUT / 2) + j * 8 + t4 * 2;
            if (r0 < N)
                *(float2*)&out[(size_t)r0 * COUT + col] = make_float2(acc[i][j][0], acc[i][j][1]);
            if (r0 + 8 < N)
                *(float2*)&out[(size_t)(r0 + 8) * COUT + col] = make_float2(acc[i][j][2], acc[i][j][3]);
        }
    }
}

// ---------------- aggregation: out = S * act  (plain, barrier-free, warp/node) ----
template<int W>
__global__ void k_agg(const float* __restrict__ act, float* __restrict__ out, int N) {
    constexpr int V = W / 32;
    int gw   = (blockIdx.x * blockDim.x + threadIdx.x) >> 5;
    int lane = threadIdx.x & 31;
    if (gw >= N) return;

    float sn = g_selfnorm[gw];
    float acc[V];
    if constexpr (V == 4) {
        float4 tv = *(const float4*)&act[(size_t)gw * W + lane * 4];
        acc[0] = sn * tv.x; acc[1] = sn * tv.y; acc[2] = sn * tv.z; acc[3] = sn * tv.w;
    } else {
        float2 tv = *(const float2*)&act[(size_t)gw * W + lane * 2];
        acc[0] = sn * tv.x; acc[1] = sn * tv.y;
    }
    int r0 = g_rowstart[gw], r1 = g_rowstart[gw + 1];
    #pragma unroll 4
    for (int e = r0; e < r1; e++) {
        Edge ed = g_csr[e];
        float nm = ed.nm;
        if constexpr (V == 4) {
            float4 v = *(const float4*)&act[(size_t)ed.s * W + lane * 4];
            acc[0] = fmaf(nm, v.x, acc[0]); acc[1] = fmaf(nm, v.y, acc[1]);
            acc[2] = fmaf(nm, v.z, acc[2]); acc[3] = fmaf(nm, v.w, acc[3]);
        } else {
            float2 v = *(const float2*)&act[(size_t)ed.s * W + lane * 2];
            acc[0] = fmaf(nm, v.x, acc[0]); acc[1] = fmaf(nm, v.y, acc[1]);
        }
    }
    if constexpr (V == 4) {
        *(float4*)&out[(size_t)gw * W + lane * 4] = make_float4(acc[0], acc[1], acc[2], acc[3]);
    } else {
        *(float2*)&out[(size_t)gw * W + lane * 2] = make_float2(acc[0], acc[1]);
    }
}

// ---------------- BN stats + fused param computation (last-block pattern) ----------
template<int COUT>
__global__ __launch_bounds__(256) void k_bnstats(const float* __restrict__ h,
                                                 const float* __restrict__ gam,
                                                 const float* __restrict__ bet,
                                                 int N, float invN) {
    constexpr int REP = 256 / COUT;
    __shared__ float s_s[256], s_q[256];
    __shared__ bool is_last;
    int t = threadIdx.x;
    int c = t & (COUT - 1);
    int rep = t / COUT;
    int chunk = (N + gridDim.x - 1) / gridDim.x;
    int lo = blockIdx.x * chunk;
    int hi = min(lo + chunk, N);
    float s = 0.f, q = 0.f;
    for (int r = lo + rep; r < hi; r += REP) {
        float v = h[(size_t)r * COUT + c];
        s += v;
        q = fmaf(v, v, q);
    }
    s_s[t] = s; s_q[t] = q;
    __syncthreads();
    if (t < COUT) {
        #pragma unroll
        for (int w = 1; w < REP; w++) { s += s_s[t + w * COUT]; q += s_q[t + w * COUT]; }
        atomicAdd(&g_bnsum[t], s);
        atomicAdd(&g_bnsq[t],  q);
    }
    __threadfence();
    if (t == 0) {
        int v = atomicAdd(&g_ticket, 1);
        is_last = (v == (int)gridDim.x - 1);
    }
    __syncthreads();
    if (is_last) {
        if (t == 0) g_ticket = 0;
        if (t < COUT) {
            float ms = atomicAdd(&g_bnsum[t], 0.f);
            float mq = atomicAdd(&g_bnsq[t], 0.f);
            float m  = ms * invN;
            float va = mq * invN - m * m;
            float inv = rsqrtf(va + 1e-5f);
            float sc = gam[t] * inv;
            g_scale[t] = sc;
            g_shift[t] = bet[t] - m * sc;
            g_bnsum[t] = 0.f;
            g_bnsq[t]  = 0.f;
        }
    }
}

// ---------------- final BN+ReLU writing d_out (LOUT channels) ----------------
__global__ void k_bnfinal(const float* __restrict__ h, float* __restrict__ out, int total) {
    int idx = blockIdx.x * blockDim.x + threadIdx.x;
    if (idx >= total) return;
    int c = idx & (LOUT - 1);
    out[idx] = fmaxf(fmaf(h[idx], g_scale[c], g_shift[c]), 0.f);
}

// ---------------- launch ----------------
extern "C" void kernel_launch(void* const* d_in, const int* in_sizes, int n_in,
                              void* d_out, int out_size) {
    const float* x   = (const float*)d_in[0];
    const void*  ei  = d_in[1];
    const float* ew  = (const float*)d_in[2];
    const float* W0  = (const float*)d_in[3];
    const float* ga0 = (const float*)d_in[5];
    const float* be0 = (const float*)d_in[6];
    const float* W1  = (const float*)d_in[7];
    const float* ga1 = (const float*)d_in[9];
    const float* be1 = (const float*)d_in[10];
    const float* Wf  = (const float*)d_in[11];
    const float* gaf = (const float*)d_in[13];
    const float* bef = (const float*)d_in[14];
    // biases d_in[4]/[8]/[12] are dead: BN mean-subtraction cancels them exactly.

    int N = in_sizes[0] / CH;
    int E = in_sizes[2];
    float invN = 1.0f / (float)N;

    float *act_ptr = nullptr, *agg_ptr = nullptr;
    cudaGetSymbolAddress((void**)&act_ptr, g_act);
    cudaGetSymbolAddress((void**)&agg_ptr, g_agg);

    // dyn smem: COUT=128: (4*2560 + 6*2560 + 256)*4 = 103424 B
    //           COUT=64 : (4*2560 + 6*1280 + 256)*4 = 72704 B
    const int SM128 = 103424, SM64 = 72704;
    cudaFuncSetAttribute(k_gemm<CH, false>, cudaFuncAttributeMaxDynamicSharedMemorySize, SM128);
    cudaFuncSetAttribute(k_gemm<CH, true>,  cudaFuncAttributeMaxDynamicSharedMemorySize, SM128);
    cudaFuncSetAttribute(k_gemm<LOUT, true>, cudaFuncAttributeMaxDynamicSharedMemorySize, SM64);

    int nb_e = (E + 255) / 256;
    int nb_scan = (N + SCHUNK - 1) / SCHUNK;
    int gemm_blocks = (N + 127) / 128;
    int agg_blocks  = (N * 32 + 255) / 256;

    // preprocessing
    k_wsplit<<<64, 256>>>(W0, W1, Wf);
    k_deg<<<nb_e, 256>>>(ei, ew, E);
    k_scan1<<<nb_scan, 256>>>(N);
    k_gemm<CH, false><<<gemm_blocks, 256, SM128>>>(x, 0, act_ptr, N);   // PROFILED SLOT (4th)
    k_scan2<<<1, 64>>>(nb_scan);
    k_scan3<<<nb_scan, 256>>>(N, E);
    k_fill<<<nb_e, 256>>>(ei, ew, E);

    // layer 0
    k_agg<CH><<<agg_blocks, 256>>>(act_ptr, agg_ptr, N);
    k_bnstats<CH><<<296, 256>>>(agg_ptr, ga0, be0, N, invN);

    // layer 1
    k_gemm<CH, true><<<gemm_blocks, 256, SM128>>>(agg_ptr, 16384, act_ptr, N);
    k_agg<CH><<<agg_blocks, 256>>>(act_ptr, agg_ptr, N);
    k_bnstats<CH><<<296, 256>>>(agg_ptr, ga1, be1, N, invN);

    // layer 2 (64-wide agg)
    k_gemm<LOUT, true><<<gemm_blocks, 256, SM64>>>(agg_ptr, 32768, act_ptr, N);
    k_agg<LOUT><<<agg_blocks, 256>>>(act_ptr, agg_ptr, N);
    k_bnstats<LOUT><<<296, 256>>>(agg_ptr, gaf, bef, N, invN);
    k_bnfinal<<<(N * LOUT + 255) / 256, 256>>>(agg_ptr, (float*)d_out, N * LOUT);
}

// round 17
// speedup vs baseline: 1.0884x; 1.0390x over previous
#include <cuda_runtime.h>
#include <cuda_fp16.h>
#include <math.h>

// ---------------- problem constants ----------------
#define NMAX 50000
#define EMAX 800000
#define CH   128
#define LOUT 64
#define SCHUNK 1024   // counts per scan block
#define BKC  16       // GEMM k-chunk

// ---------------- device scratch ----------------
struct alignas(8) Edge { int s; float nm; };
__device__ unsigned long long g_pk[NMAX];  // packed (count<<44 | wsum*2^32); zeroed by scan3
__device__ float g_dis[NMAX];
__device__ float g_selfnorm[NMAX];
__device__ int   g_rowstart[NMAX + 1];
__device__ int   g_cursor[NMAX];
__device__ int   g_partial[64];
__device__ Edge  g_csr[EMAX];
__device__ __half g_act[(size_t)NMAX * CH];   // GEMM output, fp16 (gather operand)
__device__ float g_agg[(size_t)NMAX * CH];    // agg output h, fp32
__device__ float g_bnsum[CH];
__device__ float g_bnsq[CH];
__device__ float g_scale[CH];
__device__ float g_shift[CH];
__device__ int   g_ticket;
// pre-split weights (tf32 hi/lo), N-MAJOR [n][k=128]: W0 @0, W1 @16384, Wf @32768
__device__ unsigned g_Whi[128 * (128 + 128 + 64)];
__device__ unsigned g_Wlo[128 * (128 + 128 + 64)];

// ---------------- helpers ----------------
__device__ __forceinline__ bool idx_is64(const void* ei) {
    const int* w = (const int*)ei;
    return ((w[1] | w[3] | w[5] | w[7] | w[9]) == 0);
}
__device__ __forceinline__ int fetch_idx(const void* p, long long i, bool is64) {
    if (is64) return (int)((const long long*)p)[i];
    return ((const int*)p)[i];
}
__device__ __forceinline__ void cvt2tf32(float x, unsigned& hi, unsigned& lo) {
    asm("cvt.rna.tf32.f32 %0, %1;" : "=r"(hi) : "f"(x));
    float l = x - __uint_as_float(hi);
    asm("cvt.rna.tf32.f32 %0, %1;" : "=r"(lo) : "f"(l));
}
__device__ __forceinline__ void mma_tf32(float* c, const unsigned* a, unsigned b0, unsigned b1) {
    asm volatile("mma.sync.aligned.m16n8k8.row.col.f32.tf32.tf32.f32 "
        "{%0,%1,%2,%3}, {%4,%5,%6,%7}, {%8,%9}, {%0,%1,%2,%3};"
        : "+f"(c[0]), "+f"(c[1]), "+f"(c[2]), "+f"(c[3])
        : "r"(a[0]), "r"(a[1]), "r"(a[2]), "r"(a[3]), "r"(b0), "r"(b1));
}
__device__ __forceinline__ void ldsm_x4(unsigned* r, unsigned addr) {
    asm volatile("ldmatrix.sync.aligned.m8n8.x4.shared.b16 {%0,%1,%2,%3}, [%4];"
        : "=r"(r[0]), "=r"(r[1]), "=r"(r[2]), "=r"(r[3]) : "r"(addr));
}
__device__ __forceinline__ void ldsm_x2(unsigned& r0, unsigned& r1, unsigned addr) {
    asm volatile("ldmatrix.sync.aligned.m8n8.x2.shared.b16 {%0,%1}, [%2];"
        : "=r"(r0), "=r"(r1) : "r"(addr));
}

// ---------------- weight pre-split (N-MAJOR: g_Whi[woff + n*128 + k]) ----------------
__global__ void k_wsplit(const float* __restrict__ W0, const float* __restrict__ W1,
                         const float* __restrict__ Wf) {
    int i = blockIdx.x * 256 + threadIdx.x;      // i = n*128 + k
    if (i < 128 * 128) {
        int n = i >> 7, k = i & 127;
        unsigned hi, lo;
        cvt2tf32(W0[k * 128 + n], hi, lo); g_Whi[i] = hi;         g_Wlo[i] = lo;
        cvt2tf32(W1[k * 128 + n], hi, lo); g_Whi[16384 + i] = hi; g_Wlo[16384 + i] = lo;
        if (n < 64) {
            cvt2tf32(Wf[k * 64 + n], hi, lo);
            g_Whi[32768 + i] = hi; g_Wlo[32768 + i] = lo;
        }
    }
}

// ---------------- degree + count: single packed 64-bit atomic ----------------
__global__ void k_deg(const void* ei, const float* __restrict__ ew, int E) {
    int e = blockIdx.x * blockDim.x + threadIdx.x;
    if (e >= E) return;
    bool is64 = idx_is64(ei);
    int d = fetch_idx(ei, (long long)E + e, is64);
    unsigned long long p = (1ull << 44) |
        (unsigned long long)(ew[e] * 4294967296.0f);   // w*2^32 < 2^32 (w<1)
    atomicAdd(&g_pk[d], p);
}

// ---------------- parallel scan phases ----------------
__global__ __launch_bounds__(256) void k_scan1(int N) {
    int base = blockIdx.x * SCHUNK + threadIdx.x * 4;
    int s = 0;
    #pragma unroll
    for (int k = 0; k < 4; k++) { int i = base + k; if (i < N) s += (int)(g_pk[i] >> 44); }
    #pragma unroll
    for (int o = 16; o > 0; o >>= 1) s += __shfl_down_sync(0xffffffffu, s, o);
    __shared__ int ws[8];
    if ((threadIdx.x & 31) == 0) ws[threadIdx.x >> 5] = s;
    __syncthreads();
    if (threadIdx.x < 8) {
        int v = ws[threadIdx.x];
        #pragma unroll
        for (int o = 4; o > 0; o >>= 1) v += __shfl_down_sync(0xffu, v, o, 8);
        if (threadIdx.x == 0) g_partial[blockIdx.x] = v;
    }
}

__global__ void k_scan2(int nb) {
    __shared__ int sh[64];
    int t = threadIdx.x;
    int v = (t < nb) ? g_partial[t] : 0;
    sh[t] = v;
    __syncthreads();
    #pragma unroll
    for (int o = 1; o < 64; o <<= 1) {
        int u = (t >= o) ? sh[t - o] : 0;
        __syncthreads();
        sh[t] += u;
        __syncthreads();
    }
    g_partial[t] = sh[t] - v;
}

__global__ __launch_bounds__(256) void k_scan3(int N, int E) {
    const unsigned long long M44 = (1ull << 44) - 1ull;
    int t = threadIdx.x, lane = t & 31, w = t >> 5;
    int base = blockIdx.x * SCHUNK + t * 4;
    int c[4]; unsigned long long pk[4]; int s = 0;
    #pragma unroll
    for (int k = 0; k < 4; k++) {
        int i = base + k;
        pk[k] = (i < N) ? g_pk[i] : 0ull;
        c[k] = (int)(pk[k] >> 44);
        s += c[k];
    }
    int incl = s;
    #pragma unroll
    for (int o = 1; o < 32; o <<= 1) {
        int u = __shfl_up_sync(0xffffffffu, incl, o);
        if (lane >= o) incl += u;
    }
    int wexcl = incl - s;
    __shared__ int wtot[8], woff2[8];
    if (lane == 31) wtot[w] = incl;
    __syncthreads();
    if (t < 8) {
        int v = wtot[t], iv = v;
        #pragma unroll
        for (int o = 1; o < 8; o <<= 1) {
            int u = __shfl_up_sync(0xffu, iv, o, 8);
            if (t >= o) iv += u;
        }
        woff2[t] = iv - v;
    }
    __syncthreads();
    int run = g_partial[blockIdx.x] + woff2[w] + wexcl;
    #pragma unroll
    for (int k = 0; k < 4; k++) {
        int i = base + k;
        if (i < N) {
            g_rowstart[i] = run;
            g_cursor[i]   = run;
            run += c[k];
            float deg = (float)(pk[k] & M44) * 0x1p-32f;
            float d = rsqrtf(deg + 1.0f);
            g_dis[i] = d;
            g_selfnorm[i] = d * d;
            g_pk[i] = 0ull;
        }
    }
    if (blockIdx.x == 0 && t == 0) g_rowstart[N] = E;
}

__global__ void k_fill(const void* ei, const float* __restrict__ ew, int E) {
    int e = blockIdx.x * blockDim.x + threadIdx.x;
    if (e >= E) return;
    bool is64 = idx_is64(ei);
    int s = fetch_idx(ei, e, is64);
    int d = fetch_idx(ei, (long long)E + e, is64);
    float nm = g_dis[s] * ew[e] * g_dis[d];
    int pos = atomicAdd(&g_cursor[d], 1);
    Edge ed; ed.s = s; ed.nm = nm;
    g_csr[pos] = ed;
}

// ---------------- pipelined tf32 tensor GEMM: act(fp16) = f(A)[N,128] @ W ----------
// 3-term split, ldmatrix fragments, mid-chunk staging, 2 CTAs/SM. fp16 epilogue.
template<int COUT, bool BN>
__global__ __launch_bounds__(256, 2) void k_gemm(const float* __restrict__ A, int woff,
                                                 __half* __restrict__ out, int N) {
    constexpr int AS = 20;               // A row stride (words), rows 80B (16B aligned)
    constexpr int BS = 20;               // B n-row stride (words): 16 k + 4 pad
    constexpr int NT = COUT / 16;
    constexpr int ABUF = 128 * AS;
    constexpr int BBUF = COUT * BS;
    constexpr int BITER = (COUT * 4) / 256;
    extern __shared__ unsigned smem[];
    unsigned* sA_h = smem;
    unsigned* sA_l = smem + 2 * ABUF;
    float* s_scale = (float*)(smem + 4 * ABUF + 6 * BBUF);
    float* s_shift = s_scale + 128;
    unsigned smem32 = (unsigned)__cvta_generic_to_shared(smem);

    int tid = threadIdx.x;
    int lane = tid & 31, w = tid >> 5;
    int wm = w & 3, wn = w >> 2;
    int brow = blockIdx.x * 128;
    int g = lane >> 2, t4 = lane & 3;

    if (BN) {
        if (tid < 128) { s_scale[tid] = g_scale[tid]; s_shift[tid] = g_shift[tid]; }
        __syncthreads();
    }

    unsigned aoff = ((lane & 15) * AS) * 4 + (lane >> 4) * 16;
    unsigned boff = ((lane & 7) * BS) * 4 + ((lane >> 3) & 1) * 16;

    int f1 = tid + 256;
    int row0 = tid >> 2, kc0 = (tid & 3) * 4;
    int row1 = f1 >> 2,  kc1 = (f1 & 3) * 4;
    int gr0 = brow + row0, gr1 = brow + row1;
    float4 rA0, rA1;

    auto prefA = [&](int c) {
        rA0 = (gr0 < N) ? *(const float4*)&A[(size_t)gr0 * 128 + c * BKC + kc0]
                        : make_float4(0.f, 0.f, 0.f, 0.f);
        rA1 = (gr1 < N) ? *(const float4*)&A[(size_t)gr1 * 128 + c * BKC + kc1]
                        : make_float4(0.f, 0.f, 0.f, 0.f);
    };
    auto cvtstoreA = [&](int c, int buf) {
        unsigned* dh = sA_h + buf * ABUF;
        unsigned* dl = sA_l + buf * ABUF;
        #pragma unroll
        for (int q = 0; q < 2; q++) {
            float4 v = q ? rA1 : rA0;
            int row = q ? row1 : row0;
            int kc  = q ? kc1 : kc0;
            if (BN) {
                int cb = c * BKC + kc;
                v.x = fmaxf(fmaf(v.x, s_scale[cb + 0], s_shift[cb + 0]), 0.f);
                v.y = fmaxf(fmaf(v.y, s_scale[cb + 1], s_shift[cb + 1]), 0.f);
                v.z = fmaxf(fmaf(v.z, s_scale[cb + 2], s_shift[cb + 2]), 0.f);
                v.w = fmaxf(fmaf(v.w, s_scale[cb + 3], s_shift[cb + 3]), 0.f);
            }
            unsigned hi, lo;
            int b = row * AS + kc;
            cvt2tf32(v.x, hi, lo); dh[b + 0] = hi; dl[b + 0] = lo;
            cvt2tf32(v.y, hi, lo); dh[b + 1] = hi; dl[b + 1] = lo;
            cvt2tf32(v.z, hi, lo); dh[b + 2] = hi; dl[b + 2] = lo;
            cvt2tf32(v.w, hi, lo); dh[b + 3] = hi; dl[b + 3] = lo;
        }
    };
    auto loadB = [&](int c, int buf) {
        #pragma unroll
        for (int it = 0; it < BITER; it++) {
            int f = tid + it * 256;
            int n = f >> 2;
            int seg = f & 3;
            int gidx = woff + n * 128 + c * BKC + seg * 4;
            unsigned dh = smem32 + (4 * ABUF + buf * BBUF + n * BS + seg * 4) * 4;
            unsigned dl = smem32 + (4 * ABUF + 3 * BBUF + buf * BBUF + n * BS + seg * 4) * 4;
            asm volatile("cp.async.cg.shared.global [%0], [%1], 16;" :: "r"(dh), "l"(&g_Whi[gidx]));
            asm volatile("cp.async.cg.shared.global [%0], [%1], 16;" :: "r"(dl), "l"(&g_Wlo[gidx]));
        }
        asm volatile("cp.async.commit_group;");
    };

    float acc[2][NT][4];
    #pragma unroll
    for (int i = 0; i < 2; i++)
        #pragma unroll
        for (int j = 0; j < NT; j++)
            #pragma unroll
            for (int q = 0; q < 4; q++) acc[i][j][q] = 0.f;

    auto compute_half2 = [&](int abuf, int bbuf, int ks) {
        unsigned ah[2][4], al[2][4];
        #pragma unroll
        for (int i = 0; i < 2; i++) {
            unsigned off = ((unsigned)((wm * 32 + i * 16) * AS + ks)) * 4 + aoff;
            ldsm_x4(ah[i], smem32 + (abuf * ABUF) * 4 + off);
            ldsm_x4(al[i], smem32 + ((2 + abuf) * ABUF) * 4 + off);
        }
        #pragma unroll
        for (int j = 0; j < NT; j++) {
            unsigned off = ((unsigned)((wn * (COUT / 2) + j * 8) * BS + ks)) * 4 + boff;
            unsigned bh0, bh1, bl0, bl1;
            ldsm_x2(bh0, bh1, smem32 + (4 * ABUF + bbuf * BBUF) * 4 + off);
            ldsm_x2(bl0, bl1, smem32 + (4 * ABUF + (3 + bbuf) * BBUF) * 4 + off);
            #pragma unroll
            for (int i = 0; i < 2; i++) {
                mma_tf32(acc[i][j], ah[i], bh0, bh1);   // hi*hi
                mma_tf32(acc[i][j], ah[i], bl0, bl1);   // hi*lo
                mma_tf32(acc[i][j], al[i], bh0, bh1);   // lo*hi
            }
        }
    };

    // prologue
    prefA(0);
    loadB(0, 0);
    loadB(1, 1);
    cvtstoreA(0, 0);
    prefA(1);
    asm volatile("cp.async.wait_group 1;");
    __syncthreads();

    #pragma unroll 1
    for (int c = 0; c < 8; c++) {
        int abuf = c & 1, bbuf = c % 3;
        compute_half2(abuf, bbuf, 0);
        if (c < 7) {
            cvtstoreA(c + 1, (c + 1) & 1);
            if (c < 6) { prefA(c + 2); loadB(c + 2, (c + 2) % 3); }
        }
        compute_half2(abuf, bbuf, 8);
        if (c < 7) {
            if (c < 6) asm volatile("cp.async.wait_group 1;");
            else       asm volatile("cp.async.wait_group 0;");
            __syncthreads();
        }
    }

    // fp16 epilogue: adjacent cols (t4*2, t4*2+1) -> one half2 store
    #pragma unroll
    for (int i = 0; i < 2; i++) {
        int r0 = brow + wm * 32 + i * 16 + g;
        #pragma unroll
        for (int j = 0; j < NT; j++) {
            int col = wn * (COUT / 2) + j * 8 + t4 * 2;
            if (r0 < N)
                *(__half2*)&out[(size_t)r0 * COUT + col] =
                    __floats2half2_rn(acc[i][j][0], acc[i][j][1]);
            if (r0 + 8 < N)
                *(__half2*)&out[(size_t)(r0 + 8) * COUT + col] =
                    __floats2half2_rn(acc[i][j][2], acc[i][j][3]);
        }
    }
}

// ---------------- aggregation: h(fp32) = S * act(fp16), barrier-free, warp/node ----
template<int W>
__global__ void k_agg(const __half* __restrict__ act, float* __restrict__ out, int N) {
    constexpr int V = W / 32;
    int gw   = (blockIdx.x * blockDim.x + threadIdx.x) >> 5;
    int lane = threadIdx.x & 31;
    if (gw >= N) return;

    float sn = g_selfnorm[gw];
    float acc[V];
    if constexpr (V == 4) {
        uint2 u = *(const uint2*)&act[(size_t)gw * W + lane * 4];
        float2 p0 = __half22float2(*(__half2*)&u.x);
        float2 p1 = __half22float2(*(__half2*)&u.y);
        acc[0] = sn * p0.x; acc[1] = sn * p0.y; acc[2] = sn * p1.x; acc[3] = sn * p1.y;
    } else {
        unsigned u = *(const unsigned*)&act[(size_t)gw * W + lane * 2];
        float2 p = __half22float2(*(__half2*)&u);
        acc[0] = sn * p.x; acc[1] = sn * p.y;
    }
    int r0 = g_rowstart[gw], r1 = g_rowstart[gw + 1];
    #pragma unroll 4
    for (int e = r0; e < r1; e++) {
        Edge ed = g_csr[e];
        float nm = ed.nm;
        if constexpr (V == 4) {
            uint2 u = *(const uint2*)&act[(size_t)ed.s * W + lane * 4];
            float2 p0 = __half22float2(*(__half2*)&u.x);
            float2 p1 = __half22float2(*(__half2*)&u.y);
            acc[0] = fmaf(nm, p0.x, acc[0]); acc[1] = fmaf(nm, p0.y, acc[1]);
            acc[2] = fmaf(nm, p1.x, acc[2]); acc[3] = fmaf(nm, p1.y, acc[3]);
        } else {
            unsigned u = *(const unsigned*)&act[(size_t)ed.s * W + lane * 2];
            float2 p = __half22float2(*(__half2*)&u);
            acc[0] = fmaf(nm, p.x, acc[0]); acc[1] = fmaf(nm, p.y, acc[1]);
        }
    }
    if constexpr (V == 4) {
        *(float4*)&out[(size_t)gw * W + lane * 4] = make_float4(acc[0], acc[1], acc[2], acc[3]);
    } else {
        *(float2*)&out[(size_t)gw * W + lane * 2] = make_float2(acc[0], acc[1]);
    }
}

// ---------------- BN stats + fused param computation (last-block pattern) ----------
template<int COUT>
__global__ __launch_bounds__(256) void k_bnstats(const float* __restrict__ h,
                                                 const float* __restrict__ gam,
                                                 const float* __restrict__ bet,
                                                 int N, float invN) {
    constexpr int REP = 256 / COUT;
    __shared__ float s_s[256], s_q[256];
    __shared__ bool is_last;
    int t = threadIdx.x;
    int c = t & (COUT - 1);
    int rep = t / COUT;
    int chunk = (N + gridDim.x - 1) / gridDim.x;
    int lo = blockIdx.x * chunk;
    int hi = min(lo + chunk, N);
    float s = 0.f, q = 0.f;
    for (int r = lo + rep; r < hi; r += REP) {
        float v = h[(size_t)r * COUT + c];
        s += v;
        q = fmaf(v, v, q);
    }
    s_s[t] = s; s_q[t] = q;
    __syncthreads();
    if (t < COUT) {
        #pragma unroll
        for (int w = 1; w < REP; w++) { s += s_s[t + w * COUT]; q += s_q[t + w * COUT]; }
        atomicAdd(&g_bnsum[t], s);
        atomicAdd(&g_bnsq[t],  q);
    }
    __threadfence();
    if (t == 0) {
        int v = atomicAdd(&g_ticket, 1);
        is_last = (v == (int)gridDim.x - 1);
    }
    __syncthreads();
    if (is_last) {
        if (t == 0) g_ticket = 0;
        if (t < COUT) {
            float ms = atomicAdd(&g_bnsum[t], 0.f);
            float mq = atomicAdd(&g_bnsq[t], 0.f);
            float m  = ms * invN;
            float va = mq * invN - m * m;
            float inv = rsqrtf(va + 1e-5f);
            float sc = gam[t] * inv;
            g_scale[t] = sc;
            g_shift[t] = bet[t] - m * sc;
            g_bnsum[t] = 0.f;
            g_bnsq[t]  = 0.f;
        }
    }
}

// ---------------- final BN+ReLU writing d_out (LOUT channels) ----------------
__global__ void k_bnfinal(const float* __restrict__ h, float* __restrict__ out, int total) {
    int idx = blockIdx.x * blockDim.x + threadIdx.x;
    if (idx >= total) return;
    int c = idx & (LOUT - 1);
    out[idx] = fmaxf(fmaf(h[idx], g_scale[c], g_shift[c]), 0.f);
}

// ---------------- launch ----------------
extern "C" void kernel_launch(void* const* d_in, const int* in_sizes, int n_in,
                              void* d_out, int out_size) {
    const float* x   = (const float*)d_in[0];
    const void*  ei  = d_in[1];
    const float* ew  = (const float*)d_in[2];
    const float* W0  = (const float*)d_in[3];
    const float* ga0 = (const float*)d_in[5];
    const float* be0 = (const float*)d_in[6];
    const float* W1  = (const float*)d_in[7];
    const float* ga1 = (const float*)d_in[9];
    const float* be1 = (const float*)d_in[10];
    const float* Wf  = (const float*)d_in[11];
    const float* gaf = (const float*)d_in[13];
    const float* bef = (const float*)d_in[14];
    // biases d_in[4]/[8]/[12] are dead: BN mean-subtraction cancels them exactly.

    int N = in_sizes[0] / CH;
    int E = in_sizes[2];
    float invN = 1.0f / (float)N;

    __half* act_ptr = nullptr;
    float*  agg_ptr = nullptr;
    cudaGetSymbolAddress((void**)&act_ptr, g_act);
    cudaGetSymbolAddress((void**)&agg_ptr, g_agg);

    const int SM128 = 103424, SM64 = 72704;
    cudaFuncSetAttribute(k_gemm<CH, false>, cudaFuncAttributeMaxDynamicSharedMemorySize, SM128);
    cudaFuncSetAttribute(k_gemm<CH, true>,  cudaFuncAttributeMaxDynamicSharedMemorySize, SM128);
    cudaFuncSetAttribute(k_gemm<LOUT, true>, cudaFuncAttributeMaxDynamicSharedMemorySize, SM64);

    int nb_e = (E + 255) / 256;
    int nb_scan = (N + SCHUNK - 1) / SCHUNK;
    int gemm_blocks = (N + 127) / 128;
    int agg_blocks  = (N * 32 + 255) / 256;

    // preprocessing
    k_wsplit<<<64, 256>>>(W0, W1, Wf);
    k_deg<<<nb_e, 256>>>(ei, ew, E);
    k_scan1<<<nb_scan, 256>>>(N);
    k_gemm<CH, false><<<gemm_blocks, 256, SM128>>>(x, 0, act_ptr, N);   // PROFILED SLOT (4th)
    k_scan2<<<1, 64>>>(nb_scan);
    k_scan3<<<nb_scan, 256>>>(N, E);
    k_fill<<<nb_e, 256>>>(ei, ew, E);

    // layer 0
    k_agg<CH><<<agg_blocks, 256>>>(act_ptr, agg_ptr, N);
    k_bnstats<CH><<<296, 256>>>(agg_ptr, ga0, be0, N, invN);

    // layer 1
    k_gemm<CH, true><<<gemm_blocks, 256, SM128>>>(agg_ptr, 16384, act_ptr, N);
    k_agg<CH><<<agg_blocks, 256>>>(act_ptr, agg_ptr, N);
    k_bnstats<CH><<<296, 256>>>(agg_ptr, ga1, be1, N, invN);

    // layer 2 (64-wide)
    k_gemm<LOUT, true><<<gemm_blocks, 256, SM64>>>(agg_ptr, 32768, act_ptr, N);
    k_agg<LOUT><<<agg_blocks, 256>>>(act_ptr, agg_ptr, N);
    k_bnstats<LOUT><<<296, 256>>>(agg_ptr, gaf, bef, N, invN);
    k_bnfinal<<<(N * LOUT + 255) / 256, 256>>>(agg_ptr, (float*)d_out, N * LOUT);
}